// round 1
// baseline (speedup 1.0000x reference)
#include <cuda_runtime.h>
#include <math.h>
#include <stdint.h>

// Problem constants
#define NN   100000
#define FIN  64
#define CC   128
#define HH   2
#define DD   64
#define EE   600000
#define MT   2
#define OUTD 8

// ---------------------------------------------------------------------------
// Scratch (device globals — no allocation allowed)
// ---------------------------------------------------------------------------
__device__ float    g_h[(size_t)NN * CC];       // projected features [N,C]
__device__ float    g_out0[(size_t)NN * CC];    // per-edge-type output 0
__device__ float    g_out1[(size_t)NN * CC];    // per-edge-type output 1
__device__ float    g_comb[(size_t)NN * CC];    // combined layer output
__device__ float    g_asrc[MT * NN * HH];       // [type][node][head]
__device__ float    g_adst[MT * NN * HH];
__device__ float    g_alpha[(size_t)EE * HH];   // per-edge alpha -> exp(alpha-max)
__device__ unsigned g_amax[NN * HH];            // encoded segment max
__device__ float    g_asum[NN * HH];            // segment sum of exp
__device__ float    g_colsum[MT * CC];          // semantic attn column sums
__device__ float    g_attn[MT];                 // semantic softmax weights

// ---------------------------------------------------------------------------
// Order-preserving float <-> uint encoding for atomicMax on floats
// ---------------------------------------------------------------------------
__device__ __forceinline__ unsigned fenc(float f) {
    unsigned u = __float_as_uint(f);
    return (u & 0x80000000u) ? ~u : (u | 0x80000000u);
}
__device__ __forceinline__ float fdec(unsigned u) {
    return __uint_as_float((u & 0x80000000u) ? (u ^ 0x80000000u) : ~u);
}

// ---------------------------------------------------------------------------
// Projection GEMM: out[n,c] = sum_k A[n,k] * W[k,c] + b[c]
// blockDim = 128 (one col per thread), 8 nodes per block
// ---------------------------------------------------------------------------
template <int K>
__global__ void gemm_proj_kernel(const float* __restrict__ A,
                                 const float* __restrict__ W,
                                 const float* __restrict__ b,
                                 float* __restrict__ out, int n) {
    __shared__ float sA[8][K];
    const int c = threadIdx.x;
    const int base = blockIdx.x * 8;

    for (int idx = threadIdx.x; idx < 8 * K; idx += 128) {
        int r = idx / K, k = idx - r * K;
        int row = base + r;
        sA[r][k] = (row < n) ? A[(size_t)row * K + k] : 0.0f;
    }
    __syncthreads();

    float acc[8];
#pragma unroll
    for (int j = 0; j < 8; ++j) acc[j] = 0.0f;

#pragma unroll 4
    for (int k = 0; k < K; ++k) {
        float w = W[k * CC + c];
#pragma unroll
        for (int j = 0; j < 8; ++j) acc[j] += sA[j][k] * w;
    }
    float bias = b[c];
#pragma unroll
    for (int j = 0; j < 8; ++j) {
        int row = base + j;
        if (row < n) out[(size_t)row * CC + c] = acc[j] + bias;
    }
}

// ---------------------------------------------------------------------------
// Per-node attention logits: a_src/a_dst[t][n][h] = sum_d h[n,h,d]*att[t,h,d]
// ---------------------------------------------------------------------------
__global__ void node_attn_kernel(const float* __restrict__ h,
                                 const float* __restrict__ att_src,
                                 const float* __restrict__ att_dst,
                                 float* __restrict__ asrc,
                                 float* __restrict__ adst, int n) {
    int nid = blockIdx.x * blockDim.x + threadIdx.x;
    if (nid >= n) return;
    float accs[MT][HH], accd[MT][HH];
#pragma unroll
    for (int t = 0; t < MT; ++t)
#pragma unroll
        for (int hh = 0; hh < HH; ++hh) { accs[t][hh] = 0.f; accd[t][hh] = 0.f; }

    const float* hrow = h + (size_t)nid * CC;
#pragma unroll 4
    for (int d = 0; d < DD; ++d) {
        float h0 = hrow[d];        // head 0
        float h1 = hrow[DD + d];   // head 1
#pragma unroll
        for (int t = 0; t < MT; ++t) {
            accs[t][0] += h0 * att_src[(t * HH + 0) * DD + d];
            accs[t][1] += h1 * att_src[(t * HH + 1) * DD + d];
            accd[t][0] += h0 * att_dst[(t * HH + 0) * DD + d];
            accd[t][1] += h1 * att_dst[(t * HH + 1) * DD + d];
        }
    }
#pragma unroll
    for (int t = 0; t < MT; ++t)
#pragma unroll
        for (int hh = 0; hh < HH; ++hh) {
            asrc[t * (NN * HH) + nid * HH + hh] = accs[t][hh];
            adst[t * (NN * HH) + nid * HH + hh] = accd[t][hh];
        }
}

// ---------------------------------------------------------------------------
// Edge pass 1: alpha = leaky_relu(a_src[src]+a_dst[dst]); segment max by dst
// ---------------------------------------------------------------------------
__global__ void edge_alpha_max_kernel(const int* __restrict__ ei,
                                      const float* __restrict__ asrc,
                                      const float* __restrict__ adst,
                                      float* __restrict__ alpha,
                                      unsigned* __restrict__ amax) {
    int e = blockIdx.x * blockDim.x + threadIdx.x;
    if (e >= EE) return;
    int src = ei[e];
    int dst = ei[EE + e];
#pragma unroll
    for (int hh = 0; hh < HH; ++hh) {
        float a = asrc[src * HH + hh] + adst[dst * HH + hh];
        float al = (a > 0.0f) ? a : 0.2f * a;
        alpha[(size_t)e * HH + hh] = al;
        atomicMax(&amax[dst * HH + hh], fenc(al));
    }
}

// ---------------------------------------------------------------------------
// Edge pass 2: e = exp(alpha - max[dst]); segment sum by dst (overwrites alpha)
// ---------------------------------------------------------------------------
__global__ void edge_exp_sum_kernel(const int* __restrict__ ei,
                                    float* __restrict__ alpha,
                                    const unsigned* __restrict__ amax,
                                    float* __restrict__ asum) {
    int e = blockIdx.x * blockDim.x + threadIdx.x;
    if (e >= EE) return;
    int dst = ei[EE + e];
#pragma unroll
    for (int hh = 0; hh < HH; ++hh) {
        float m = fdec(amax[dst * HH + hh]);
        float ex = expf(alpha[(size_t)e * HH + hh] - m);
        alpha[(size_t)e * HH + hh] = ex;
        atomicAdd(&asum[dst * HH + hh], ex);
    }
}

// ---------------------------------------------------------------------------
// Edge pass 3: out[dst] += h[src] * (exp / (sum[dst]+1e-16))  (32 lanes/edge)
// ---------------------------------------------------------------------------
__global__ void edge_message_kernel(const int* __restrict__ ei,
                                    const float* __restrict__ expalpha,
                                    const float* __restrict__ asum,
                                    const float* __restrict__ h,
                                    float* __restrict__ outT) {
    int gid = blockIdx.x * blockDim.x + threadIdx.x;
    int e = gid >> 5;
    int lane = gid & 31;
    if (e >= EE) return;
    int src = ei[e];
    int dst = ei[EE + e];
    int head = lane >> 4;  // lanes 0..15 -> head 0 (cols 0..63), 16..31 -> head 1
    float coef = expalpha[(size_t)e * HH + head] /
                 (asum[dst * HH + head] + 1e-16f);
    const float4* hrow = reinterpret_cast<const float4*>(h + (size_t)src * CC);
    float4 v = hrow[lane];
    float* o = outT + (size_t)dst * CC + lane * 4;
    atomicAdd(o + 0, v.x * coef);
    atomicAdd(o + 1, v.y * coef);
    atomicAdd(o + 2, v.z * coef);
    atomicAdd(o + 3, v.w * coef);
}

// ---------------------------------------------------------------------------
// Semantic GEMM: colsum[c] += sum_nodes tanh( relu(out[n,:]) @ kw[:,c] + kb[c] )
// ---------------------------------------------------------------------------
__global__ void semantic_gemm_kernel(const float* __restrict__ outT,
                                     const float* __restrict__ kw,
                                     const float* __restrict__ kb,
                                     float* __restrict__ colsum, int n) {
    __shared__ float sA[8][CC];
    const int c = threadIdx.x;
    const int base = blockIdx.x * 8;

    for (int idx = threadIdx.x; idx < 8 * CC; idx += 128) {
        int r = idx >> 7, k = idx & 127;
        int row = base + r;
        sA[r][k] = (row < n) ? fmaxf(outT[(size_t)row * CC + k], 0.0f) : 0.0f;
    }
    __syncthreads();

    float acc[8];
#pragma unroll
    for (int j = 0; j < 8; ++j) acc[j] = 0.0f;

#pragma unroll 4
    for (int k = 0; k < CC; ++k) {
        float w = kw[k * CC + c];
#pragma unroll
        for (int j = 0; j < 8; ++j) acc[j] += sA[j][k] * w;
    }
    float bias = kb[c];
    float local = 0.0f;
#pragma unroll
    for (int j = 0; j < 8; ++j) {
        int row = base + j;
        if (row < n) local += tanhf(acc[j] + bias);
    }
    atomicAdd(&colsum[c], local);
}

// ---------------------------------------------------------------------------
// Semantic score + softmax (single block, 128 threads)
// ---------------------------------------------------------------------------
__global__ void score_softmax_kernel(const float* __restrict__ q,
                                     const float* __restrict__ colsum,
                                     float* __restrict__ attn) {
    __shared__ float red[128];
    int c = threadIdx.x;
    float s[MT];
#pragma unroll
    for (int m = 0; m < MT; ++m) {
        red[c] = q[c] * colsum[m * CC + c];
        __syncthreads();
        for (int off = 64; off > 0; off >>= 1) {
            if (c < off) red[c] += red[c + off];
            __syncthreads();
        }
        s[m] = red[0] * (1.0f / (float)NN);
        __syncthreads();
    }
    if (c == 0) {
        float mx = fmaxf(s[0], s[1]);
        float e0 = expf(s[0] - mx), e1 = expf(s[1] - mx);
        float inv = 1.0f / (e0 + e1);
        attn[0] = e0 * inv;
        attn[1] = e1 * inv;
    }
}

// ---------------------------------------------------------------------------
// Combine: comb = attn0*relu(out0) + attn1*relu(out1)
// (post-layer relu is the identity: weights > 0, relu'd inputs >= 0)
// ---------------------------------------------------------------------------
__global__ void combine_kernel(const float* __restrict__ o0,
                               const float* __restrict__ o1,
                               const float* __restrict__ attn,
                               float* __restrict__ comb, size_t total) {
    size_t i = (size_t)blockIdx.x * blockDim.x + threadIdx.x;
    if (i >= total) return;
    float a0 = attn[0], a1 = attn[1];
    comb[i] = a0 * fmaxf(o0[i], 0.0f) + a1 * fmaxf(o1[i], 0.0f);
}

// ---------------------------------------------------------------------------
// Final linear: out[n,o] = comb[n,:] @ lin_w[:,o] + lin_b[o]
// ---------------------------------------------------------------------------
__global__ void final_linear_kernel(const float* __restrict__ comb,
                                    const float* __restrict__ lw,
                                    const float* __restrict__ lb,
                                    float* __restrict__ out, int n) {
    int idx = blockIdx.x * blockDim.x + threadIdx.x;
    int node = idx >> 3;
    int o = idx & 7;
    if (node >= n) return;
    float acc = lb[o];
    const float* row = comb + (size_t)node * CC;
#pragma unroll 8
    for (int k = 0; k < CC; ++k) acc += row[k] * lw[k * OUTD + o];
    out[(size_t)node * OUTD + o] = acc;
}

// ---------------------------------------------------------------------------
// Host side
// ---------------------------------------------------------------------------
struct Scratch {
    float* h; float* out0; float* out1; float* comb;
    float* asrc; float* adst; float* alpha;
    unsigned* amax; float* asum; float* colsum; float* attn;
};

static void run_han_layer(const float* input, int Kin,
                          const float* pw, const float* pb,
                          const float* att_src, const float* att_dst,
                          const float* q, const float* kw, const float* kb,
                          const int* ei0, const int* ei1, const Scratch& S) {
    // 1. projection
    if (Kin == 64)
        gemm_proj_kernel<64><<<(NN + 7) / 8, 128>>>(input, pw, pb, S.h, NN);
    else
        gemm_proj_kernel<128><<<(NN + 7) / 8, 128>>>(input, pw, pb, S.h, NN);

    // 2. per-node attention logits (both edge types)
    node_attn_kernel<<<(NN + 255) / 256, 256>>>(S.h, att_src, att_dst,
                                                S.asrc, S.adst, NN);

    cudaMemsetAsync(S.colsum, 0, MT * CC * sizeof(float));

    const int* eis[2] = {ei0, ei1};
    float* outs[2] = {S.out0, S.out1};
    for (int t = 0; t < MT; ++t) {
        cudaMemsetAsync(S.amax, 0, NN * HH * sizeof(unsigned));
        cudaMemsetAsync(S.asum, 0, NN * HH * sizeof(float));
        cudaMemsetAsync(outs[t], 0, (size_t)NN * CC * sizeof(float));

        const float* asrc_t = S.asrc + t * (NN * HH);
        const float* adst_t = S.adst + t * (NN * HH);

        edge_alpha_max_kernel<<<(EE + 255) / 256, 256>>>(eis[t], asrc_t, adst_t,
                                                         S.alpha, S.amax);
        edge_exp_sum_kernel<<<(EE + 255) / 256, 256>>>(eis[t], S.alpha,
                                                       S.amax, S.asum);
        edge_message_kernel<<<(EE * 32 + 255) / 256, 256>>>(eis[t], S.alpha,
                                                            S.asum, S.h, outs[t]);
        semantic_gemm_kernel<<<(NN + 7) / 8, 128>>>(outs[t], kw, kb,
                                                    S.colsum + t * CC, NN);
    }

    score_softmax_kernel<<<1, 128>>>(q, S.colsum, S.attn);
    combine_kernel<<<(int)(((size_t)NN * CC + 255) / 256), 256>>>(
        S.out0, S.out1, S.attn, S.comb, (size_t)NN * CC);
}

extern "C" void kernel_launch(void* const* d_in, const int* in_sizes, int n_in,
                              void* d_out, int out_size) {
    // Resolve inputs by element count (robust to dict- vs signature-order).
    const float *x = nullptr, *p1w = nullptr, *p2w = nullptr;
    const float *b128[6] = {nullptr};   // p1_proj_b, p1_q, p1_kb, p2_proj_b, p2_q, p2_kb
    const float *a256[4] = {nullptr};   // p1_att_src, p1_att_dst, p2_att_src, p2_att_dst
    const float *w16384[3] = {nullptr}; // p1_kw, p2_proj_w, p2_kw
    const float *lin_w = nullptr, *lin_b = nullptr;
    const int *ei[2] = {nullptr, nullptr};
    int n128 = 0, n256 = 0, n16384 = 0, nei = 0;

    for (int i = 0; i < n_in; ++i) {
        int sz = in_sizes[i];
        const void* p = d_in[i];
        switch (sz) {
            case NN * FIN:      x = (const float*)p; break;
            case 2 * EE:        if (nei < 2) ei[nei++] = (const int*)p; break;
            case FIN * CC:      p1w = (const float*)p; break;
            case CC * CC:       if (n16384 < 3) w16384[n16384++] = (const float*)p; break;
            case MT * HH * DD:  if (n256 < 4) a256[n256++] = (const float*)p; break;
            case CC:            if (n128 < 6) b128[n128++] = (const float*)p; break;
            case CC * OUTD:     lin_w = (const float*)p; break;
            case OUTD:          lin_b = (const float*)p; break;
            default: break;
        }
    }
    const float* p1_kw = w16384[0];
    p2w = w16384[1];
    const float* p2_kw = w16384[2];
    const float *p1_pb = b128[0], *p1_q = b128[1], *p1_kb = b128[2];
    const float *p2_pb = b128[3], *p2_q = b128[4], *p2_kb = b128[5];
    const float *p1_as = a256[0], *p1_ad = a256[1];
    const float *p2_as = a256[2], *p2_ad = a256[3];

    Scratch S;
    cudaGetSymbolAddress((void**)&S.h, g_h);
    cudaGetSymbolAddress((void**)&S.out0, g_out0);
    cudaGetSymbolAddress((void**)&S.out1, g_out1);
    cudaGetSymbolAddress((void**)&S.comb, g_comb);
    cudaGetSymbolAddress((void**)&S.asrc, g_asrc);
    cudaGetSymbolAddress((void**)&S.adst, g_adst);
    cudaGetSymbolAddress((void**)&S.alpha, g_alpha);
    cudaGetSymbolAddress((void**)&S.amax, g_amax);
    cudaGetSymbolAddress((void**)&S.asum, g_asum);
    cudaGetSymbolAddress((void**)&S.colsum, g_colsum);
    cudaGetSymbolAddress((void**)&S.attn, g_attn);

    // Layer 1: IN=64 -> C=128
    run_han_layer(x, 64, p1w, p1_pb, p1_as, p1_ad, p1_q, p1_kw, p1_kb,
                  ei[0], ei[1], S);
    // Layer 2: C=128 -> C=128 (input = g_comb; proj reads it before combine rewrites it)
    run_han_layer(S.comb, 128, p2w, p2_pb, p2_as, p2_ad, p2_q, p2_kw, p2_kb,
                  ei[0], ei[1], S);

    // Final classifier
    final_linear_kernel<<<(NN * OUTD + 255) / 256, 256>>>(
        S.comb, lin_w, lin_b, (float*)d_out, NN);
}

// round 2
// speedup vs baseline: 1.4729x; 1.4729x over previous
#include <cuda_runtime.h>
#include <math.h>
#include <stdint.h>

// Problem constants
#define NN   100000
#define FIN  64
#define CC   128
#define HH   2
#define DD   64
#define EE   600000
#define MT   2
#define OUTD 8

// NN is divisible by 32 (100000 = 3125*32) -> no row bounds checks in GEMMs.

// ---------------------------------------------------------------------------
// Scratch (device globals — no allocation allowed)
// ---------------------------------------------------------------------------
__device__ float    g_h[(size_t)NN * CC];
__device__ float    g_out0[(size_t)NN * CC];
__device__ float    g_out1[(size_t)NN * CC];
__device__ float    g_comb[(size_t)NN * CC];
__device__ float    g_asrc[MT * NN * HH];
__device__ float    g_adst[MT * NN * HH];
__device__ float    g_alpha[(size_t)EE * HH];
__device__ unsigned g_amax[NN * HH];
__device__ float    g_asum[NN * HH];
__device__ float    g_colsum[MT * CC];
__device__ float    g_attn[MT];

// ---------------------------------------------------------------------------
// Helpers
// ---------------------------------------------------------------------------
__device__ __forceinline__ unsigned fenc(float f) {
    unsigned u = __float_as_uint(f);
    return (u & 0x80000000u) ? ~u : (u | 0x80000000u);
}
__device__ __forceinline__ float fdec(unsigned u) {
    return __uint_as_float((u & 0x80000000u) ? (u ^ 0x80000000u) : ~u);
}
__device__ __forceinline__ uint64_t splat2(float x) {
    uint64_t r;
    asm("mov.b64 %0, {%1, %1};" : "=l"(r) : "f"(x));
    return r;
}
__device__ __forceinline__ void fma2(uint64_t& acc, uint64_t a, uint64_t b) {
    asm("fma.rn.f32x2 %0, %1, %2, %0;" : "+l"(acc) : "l"(a), "l"(b));
}
__device__ __forceinline__ float2 unpack2(uint64_t v) {
    float2 f;
    asm("mov.b64 {%0, %1}, %2;" : "=f"(f.x), "=f"(f.y) : "l"(v));
    return f;
}
__device__ __forceinline__ float tanh_fast(float x) {
    float y;
    asm("tanh.approx.f32 %0, %1;" : "=f"(y) : "f"(x));
    return y;
}
__device__ __forceinline__ void red_add_v4(float* p, float x, float y, float z, float w) {
    asm volatile("red.global.add.v4.f32 [%0], {%1,%2,%3,%4};"
                 :: "l"(p), "f"(x), "f"(y), "f"(z), "f"(w) : "memory");
}
__device__ __forceinline__ void red_add_v2(float* p, float x, float y) {
    asm volatile("red.global.add.v2.f32 [%0], {%1,%2};"
                 :: "l"(p), "f"(x), "f"(y) : "memory");
}

// ---------------------------------------------------------------------------
// Projection GEMM: out[n,c] = A[n,:K] @ W[K,128] + b[c]
// Persistent blocks, W fully staged in shared, 32-row A tiles,
// 4x4 thread tile with packed f32x2 FMAs.
// ---------------------------------------------------------------------------
template <int K>
__global__ void gemm_proj_kernel(const float* __restrict__ A,
                                 const float* __restrict__ W,
                                 const float* __restrict__ b,
                                 float* __restrict__ out) {
    extern __shared__ float smem[];
    float* sW = smem;             // [K][128]
    float* sA = smem + K * 128;   // [32][K]
    const int tid = threadIdx.x;
    const int cg = tid & 31;      // columns 4cg..4cg+3
    const int rg = tid >> 5;      // rows 4rg..4rg+3

    for (int idx = tid; idx < K * 128; idx += 256) sW[idx] = W[idx];
    float4 b4 = *(const float4*)&b[cg * 4];

    const int ntiles = NN / 32;
    for (int tile = blockIdx.x; tile < ntiles; tile += gridDim.x) {
        __syncthreads();
        const float* Atile = A + (size_t)tile * 32 * K;
        for (int idx = tid; idx < 32 * K; idx += 256) sA[idx] = Atile[idx];
        __syncthreads();

        uint64_t acc[4][2];
#pragma unroll
        for (int r = 0; r < 4; ++r) { acc[r][0] = 0ull; acc[r][1] = 0ull; }

#pragma unroll 2
        for (int k4 = 0; k4 < K; k4 += 4) {
            float4 a[4];
#pragma unroll
            for (int r = 0; r < 4; ++r)
                a[r] = *(const float4*)&sA[(4 * rg + r) * K + k4];
#pragma unroll
            for (int kk = 0; kk < 4; ++kk) {
                ulonglong2 wv = *(const ulonglong2*)&sW[(k4 + kk) * 128 + cg * 4];
#pragma unroll
                for (int r = 0; r < 4; ++r) {
                    float av = (kk == 0) ? a[r].x : (kk == 1) ? a[r].y
                             : (kk == 2) ? a[r].z : a[r].w;
                    uint64_t a2 = splat2(av);
                    fma2(acc[r][0], a2, wv.x);
                    fma2(acc[r][1], a2, wv.y);
                }
            }
        }
#pragma unroll
        for (int r = 0; r < 4; ++r) {
            float2 p0 = unpack2(acc[r][0]);
            float2 p1 = unpack2(acc[r][1]);
            float4 o = make_float4(p0.x + b4.x, p0.y + b4.y, p1.x + b4.z, p1.y + b4.w);
            int row = tile * 32 + 4 * rg + r;
            *(float4*)&out[(size_t)row * 128 + cg * 4] = o;
        }
    }
}

// ---------------------------------------------------------------------------
// Semantic GEMM: colsum[c] += sum_n tanh( relu(out[n,:]) @ kw[:,c] + kb[c] )
// Same tiling; relu applied on A load; tanh.approx epilogue; block-level
// shared reduction then one global atomic per column per block.
// ---------------------------------------------------------------------------
__global__ void semantic_gemm_kernel(const float* __restrict__ A,
                                     const float* __restrict__ kw,
                                     const float* __restrict__ kb,
                                     float* __restrict__ colsum) {
    extern __shared__ float smem[];
    float* sW = smem;               // [128][128]
    float* sA = smem + 128 * 128;   // [32][128]
    __shared__ float scol[128];
    const int tid = threadIdx.x;
    const int cg = tid & 31;
    const int rg = tid >> 5;

    for (int idx = tid; idx < 128 * 128; idx += 256) sW[idx] = kw[idx];
    if (tid < 128) scol[tid] = 0.0f;
    float4 kb4 = *(const float4*)&kb[cg * 4];

    float tsum[4] = {0.f, 0.f, 0.f, 0.f};

    const int ntiles = NN / 32;
    for (int tile = blockIdx.x; tile < ntiles; tile += gridDim.x) {
        __syncthreads();
        const float* Atile = A + (size_t)tile * 32 * 128;
        for (int idx = tid; idx < 32 * 128; idx += 256)
            sA[idx] = fmaxf(Atile[idx], 0.0f);
        __syncthreads();

        uint64_t acc[4][2];
#pragma unroll
        for (int r = 0; r < 4; ++r) { acc[r][0] = 0ull; acc[r][1] = 0ull; }

#pragma unroll 2
        for (int k4 = 0; k4 < 128; k4 += 4) {
            float4 a[4];
#pragma unroll
            for (int r = 0; r < 4; ++r)
                a[r] = *(const float4*)&sA[(4 * rg + r) * 128 + k4];
#pragma unroll
            for (int kk = 0; kk < 4; ++kk) {
                ulonglong2 wv = *(const ulonglong2*)&sW[(k4 + kk) * 128 + cg * 4];
#pragma unroll
                for (int r = 0; r < 4; ++r) {
                    float av = (kk == 0) ? a[r].x : (kk == 1) ? a[r].y
                             : (kk == 2) ? a[r].z : a[r].w;
                    uint64_t a2 = splat2(av);
                    fma2(acc[r][0], a2, wv.x);
                    fma2(acc[r][1], a2, wv.y);
                }
            }
        }
#pragma unroll
        for (int r = 0; r < 4; ++r) {
            float2 p0 = unpack2(acc[r][0]);
            float2 p1 = unpack2(acc[r][1]);
            tsum[0] += tanh_fast(p0.x + kb4.x);
            tsum[1] += tanh_fast(p0.y + kb4.y);
            tsum[2] += tanh_fast(p1.x + kb4.z);
            tsum[3] += tanh_fast(p1.y + kb4.w);
        }
    }
    __syncthreads();
#pragma unroll
    for (int j = 0; j < 4; ++j) atomicAdd(&scol[cg * 4 + j], tsum[j]);
    __syncthreads();
    if (tid < 128) atomicAdd(&colsum[tid], scol[tid]);
}

// ---------------------------------------------------------------------------
// Per-node attention logits, warp per node (coalesced row reads)
// ---------------------------------------------------------------------------
__global__ void node_attn_kernel(const float* __restrict__ h,
                                 const float* __restrict__ att_src,
                                 const float* __restrict__ att_dst,
                                 float* __restrict__ asrc,
                                 float* __restrict__ adst, int n) {
    int gid = blockIdx.x * blockDim.x + threadIdx.x;
    int node = gid >> 5;
    int lane = gid & 31;
    if (node >= n) return;
    const float* hrow = h + (size_t)node * CC;
    float h00 = hrow[lane];
    float h01 = hrow[lane + 32];
    float h10 = hrow[lane + 64];
    float h11 = hrow[lane + 96];

    float r[8];
#pragma unroll
    for (int t = 0; t < MT; ++t) {
        const float* as = att_src + t * CC;
        const float* ad = att_dst + t * CC;
        r[t * 4 + 0] = h00 * as[lane] + h01 * as[lane + 32];        // src head0
        r[t * 4 + 1] = h10 * as[lane + 64] + h11 * as[lane + 96];   // src head1
        r[t * 4 + 2] = h00 * ad[lane] + h01 * ad[lane + 32];        // dst head0
        r[t * 4 + 3] = h10 * ad[lane + 64] + h11 * ad[lane + 96];   // dst head1
    }
#pragma unroll
    for (int i = 0; i < 8; ++i) {
#pragma unroll
        for (int off = 16; off > 0; off >>= 1)
            r[i] += __shfl_xor_sync(0xffffffffu, r[i], off);
    }
    if (lane == 0) {
#pragma unroll
        for (int t = 0; t < MT; ++t) {
            asrc[t * (NN * HH) + node * HH + 0] = r[t * 4 + 0];
            asrc[t * (NN * HH) + node * HH + 1] = r[t * 4 + 1];
            adst[t * (NN * HH) + node * HH + 0] = r[t * 4 + 2];
            adst[t * (NN * HH) + node * HH + 1] = r[t * 4 + 3];
        }
    }
}

// ---------------------------------------------------------------------------
// Edge pass 1: alpha = leaky_relu(a_src[src]+a_dst[dst]); segment max by dst
// ---------------------------------------------------------------------------
__global__ void edge_alpha_max_kernel(const int* __restrict__ ei,
                                      const float* __restrict__ asrc,
                                      const float* __restrict__ adst,
                                      float* __restrict__ alpha,
                                      unsigned* __restrict__ amax) {
    int e = blockIdx.x * blockDim.x + threadIdx.x;
    if (e >= EE) return;
    int src = ei[e];
    int dst = ei[EE + e];
    float a0 = asrc[src * HH + 0] + adst[dst * HH + 0];
    float a1 = asrc[src * HH + 1] + adst[dst * HH + 1];
    float l0 = (a0 > 0.0f) ? a0 : 0.2f * a0;
    float l1 = (a1 > 0.0f) ? a1 : 0.2f * a1;
    *(float2*)&alpha[(size_t)e * HH] = make_float2(l0, l1);
    atomicMax(&amax[dst * HH + 0], fenc(l0));
    atomicMax(&amax[dst * HH + 1], fenc(l1));
}

// ---------------------------------------------------------------------------
// Edge pass 2: e = exp(alpha - max[dst]); segment sum by dst (v2 red)
// ---------------------------------------------------------------------------
__global__ void edge_exp_sum_kernel(const int* __restrict__ ei,
                                    float* __restrict__ alpha,
                                    const unsigned* __restrict__ amax,
                                    float* __restrict__ asum) {
    int e = blockIdx.x * blockDim.x + threadIdx.x;
    if (e >= EE) return;
    int dst = ei[EE + e];
    float2 al = *(float2*)&alpha[(size_t)e * HH];
    float ex0 = expf(al.x - fdec(amax[dst * HH + 0]));
    float ex1 = expf(al.y - fdec(amax[dst * HH + 1]));
    *(float2*)&alpha[(size_t)e * HH] = make_float2(ex0, ex1);
    red_add_v2(&asum[dst * HH], ex0, ex1);
}

// ---------------------------------------------------------------------------
// Edge pass 3: out[dst] += h[src] * coef   (32 lanes/edge, v4 reductions)
// ---------------------------------------------------------------------------
__global__ void edge_message_kernel(const int* __restrict__ ei,
                                    const float* __restrict__ expalpha,
                                    const float* __restrict__ asum,
                                    const float* __restrict__ h,
                                    float* __restrict__ outT) {
    int gid = blockIdx.x * blockDim.x + threadIdx.x;
    int e = gid >> 5;
    int lane = gid & 31;
    if (e >= EE) return;
    int src = ei[e];
    int dst = ei[EE + e];
    int head = lane >> 4;
    float coef = expalpha[(size_t)e * HH + head] /
                 (asum[dst * HH + head] + 1e-16f);
    const float4* hrow = reinterpret_cast<const float4*>(h + (size_t)src * CC);
    float4 v = hrow[lane];
    float* o = outT + (size_t)dst * CC + lane * 4;
    red_add_v4(o, v.x * coef, v.y * coef, v.z * coef, v.w * coef);
}

// ---------------------------------------------------------------------------
// Semantic score + softmax (single block, 128 threads)
// ---------------------------------------------------------------------------
__global__ void score_softmax_kernel(const float* __restrict__ q,
                                     const float* __restrict__ colsum,
                                     float* __restrict__ attn) {
    __shared__ float red[128];
    int c = threadIdx.x;
    float s[MT];
#pragma unroll
    for (int m = 0; m < MT; ++m) {
        red[c] = q[c] * colsum[m * CC + c];
        __syncthreads();
        for (int off = 64; off > 0; off >>= 1) {
            if (c < off) red[c] += red[c + off];
            __syncthreads();
        }
        s[m] = red[0] * (1.0f / (float)NN);
        __syncthreads();
    }
    if (c == 0) {
        float mx = fmaxf(s[0], s[1]);
        float e0 = expf(s[0] - mx), e1 = expf(s[1] - mx);
        float inv = 1.0f / (e0 + e1);
        attn[0] = e0 * inv;
        attn[1] = e1 * inv;
    }
}

// ---------------------------------------------------------------------------
// Combine: comb = attn0*relu(out0) + attn1*relu(out1)   (vectorized)
// ---------------------------------------------------------------------------
__global__ void combine_kernel(const float4* __restrict__ o0,
                               const float4* __restrict__ o1,
                               const float* __restrict__ attn,
                               float4* __restrict__ comb, int total4) {
    int i = blockIdx.x * blockDim.x + threadIdx.x;
    if (i >= total4) return;
    float a0 = attn[0], a1 = attn[1];
    float4 u = o0[i], v = o1[i];
    float4 r;
    r.x = a0 * fmaxf(u.x, 0.f) + a1 * fmaxf(v.x, 0.f);
    r.y = a0 * fmaxf(u.y, 0.f) + a1 * fmaxf(v.y, 0.f);
    r.z = a0 * fmaxf(u.z, 0.f) + a1 * fmaxf(v.z, 0.f);
    r.w = a0 * fmaxf(u.w, 0.f) + a1 * fmaxf(v.w, 0.f);
    comb[i] = r;
}

// ---------------------------------------------------------------------------
// Final linear
// ---------------------------------------------------------------------------
__global__ void final_linear_kernel(const float* __restrict__ comb,
                                    const float* __restrict__ lw,
                                    const float* __restrict__ lb,
                                    float* __restrict__ out, int n) {
    int idx = blockIdx.x * blockDim.x + threadIdx.x;
    int node = idx >> 3;
    int o = idx & 7;
    if (node >= n) return;
    float acc = lb[o];
    const float* row = comb + (size_t)node * CC;
#pragma unroll 8
    for (int k = 0; k < CC; ++k) acc += row[k] * lw[k * OUTD + o];
    out[(size_t)node * OUTD + o] = acc;
}

// ---------------------------------------------------------------------------
// Host side
// ---------------------------------------------------------------------------
struct Scratch {
    float* h; float* out0; float* out1; float* comb;
    float* asrc; float* adst; float* alpha;
    unsigned* amax; float* asum; float* colsum; float* attn;
};

#define GEMM_BLOCKS 296
#define GEMM_SMEM(K) ((size_t)((K) * 128 + 32 * (K)) * sizeof(float))

static void run_han_layer(const float* input, int Kin,
                          const float* pw, const float* pb,
                          const float* att_src, const float* att_dst,
                          const float* q, const float* kw, const float* kb,
                          const int* ei0, const int* ei1, const Scratch& S) {
    if (Kin == 64)
        gemm_proj_kernel<64><<<GEMM_BLOCKS, 256, GEMM_SMEM(64)>>>(input, pw, pb, S.h);
    else
        gemm_proj_kernel<128><<<GEMM_BLOCKS, 256, GEMM_SMEM(128)>>>(input, pw, pb, S.h);

    node_attn_kernel<<<(NN * 32 + 255) / 256, 256>>>(S.h, att_src, att_dst,
                                                     S.asrc, S.adst, NN);

    cudaMemsetAsync(S.colsum, 0, MT * CC * sizeof(float));

    const int* eis[2] = {ei0, ei1};
    float* outs[2] = {S.out0, S.out1};
    for (int t = 0; t < MT; ++t) {
        cudaMemsetAsync(S.amax, 0, NN * HH * sizeof(unsigned));
        cudaMemsetAsync(S.asum, 0, NN * HH * sizeof(float));
        cudaMemsetAsync(outs[t], 0, (size_t)NN * CC * sizeof(float));

        const float* asrc_t = S.asrc + t * (NN * HH);
        const float* adst_t = S.adst + t * (NN * HH);

        edge_alpha_max_kernel<<<(EE + 255) / 256, 256>>>(eis[t], asrc_t, adst_t,
                                                         S.alpha, S.amax);
        edge_exp_sum_kernel<<<(EE + 255) / 256, 256>>>(eis[t], S.alpha,
                                                       S.amax, S.asum);
        edge_message_kernel<<<(EE * 32 + 255) / 256, 256>>>(eis[t], S.alpha,
                                                            S.asum, S.h, outs[t]);
        semantic_gemm_kernel<<<GEMM_BLOCKS, 256, GEMM_SMEM(128)>>>(
            outs[t], kw, kb, S.colsum + t * CC);
    }

    score_softmax_kernel<<<1, 128>>>(q, S.colsum, S.attn);
    combine_kernel<<<(NN * CC / 4 + 255) / 256, 256>>>(
        (const float4*)S.out0, (const float4*)S.out1, S.attn,
        (float4*)S.comb, NN * CC / 4);
}

extern "C" void kernel_launch(void* const* d_in, const int* in_sizes, int n_in,
                              void* d_out, int out_size) {
    const float *x = nullptr, *p1w = nullptr;
    const float *b128[6] = {nullptr};
    const float *a256[4] = {nullptr};
    const float *w16384[3] = {nullptr};
    const float *lin_w = nullptr, *lin_b = nullptr;
    const int *ei[2] = {nullptr, nullptr};
    int n128 = 0, n256 = 0, n16384 = 0, nei = 0;

    for (int i = 0; i < n_in; ++i) {
        int sz = in_sizes[i];
        const void* p = d_in[i];
        switch (sz) {
            case NN * FIN:      x = (const float*)p; break;
            case 2 * EE:        if (nei < 2) ei[nei++] = (const int*)p; break;
            case FIN * CC:      p1w = (const float*)p; break;
            case CC * CC:       if (n16384 < 3) w16384[n16384++] = (const float*)p; break;
            case MT * HH * DD:  if (n256 < 4) a256[n256++] = (const float*)p; break;
            case CC:            if (n128 < 6) b128[n128++] = (const float*)p; break;
            case CC * OUTD:     lin_w = (const float*)p; break;
            case OUTD:          lin_b = (const float*)p; break;
            default: break;
        }
    }
    const float* p1_kw = w16384[0];
    const float* p2w   = w16384[1];
    const float* p2_kw = w16384[2];
    const float *p1_pb = b128[0], *p1_q = b128[1], *p1_kb = b128[2];
    const float *p2_pb = b128[3], *p2_q = b128[4], *p2_kb = b128[5];
    const float *p1_as = a256[0], *p1_ad = a256[1];
    const float *p2_as = a256[2], *p2_ad = a256[3];

    cudaFuncSetAttribute(gemm_proj_kernel<64>,
                         cudaFuncAttributeMaxDynamicSharedMemorySize, 100 * 1024);
    cudaFuncSetAttribute(gemm_proj_kernel<128>,
                         cudaFuncAttributeMaxDynamicSharedMemorySize, 100 * 1024);
    cudaFuncSetAttribute(semantic_gemm_kernel,
                         cudaFuncAttributeMaxDynamicSharedMemorySize, 100 * 1024);

    Scratch S;
    cudaGetSymbolAddress((void**)&S.h, g_h);
    cudaGetSymbolAddress((void**)&S.out0, g_out0);
    cudaGetSymbolAddress((void**)&S.out1, g_out1);
    cudaGetSymbolAddress((void**)&S.comb, g_comb);
    cudaGetSymbolAddress((void**)&S.asrc, g_asrc);
    cudaGetSymbolAddress((void**)&S.adst, g_adst);
    cudaGetSymbolAddress((void**)&S.alpha, g_alpha);
    cudaGetSymbolAddress((void**)&S.amax, g_amax);
    cudaGetSymbolAddress((void**)&S.asum, g_asum);
    cudaGetSymbolAddress((void**)&S.colsum, g_colsum);
    cudaGetSymbolAddress((void**)&S.attn, g_attn);

    run_han_layer(x, 64, p1w, p1_pb, p1_as, p1_ad, p1_q, p1_kw, p1_kb,
                  ei[0], ei[1], S);
    run_han_layer(S.comb, 128, p2w, p2_pb, p2_as, p2_ad, p2_q, p2_kw, p2_kb,
                  ei[0], ei[1], S);

    final_linear_kernel<<<(NN * OUTD + 255) / 256, 256>>>(
        S.comb, lin_w, lin_b, (float*)d_out, NN);
}